// round 8
// baseline (speedup 1.0000x reference)
#include <cuda_runtime.h>
#include <math.h>

#define NBK  5
#define HD   32
#define DIN  4
#define TT   25
#define HIDD 64
#define TPB  256          // 8 warps
#define COLS 32           // lanes = sample columns
#define SPT  4            // samples per thread (float4-packed)
#define SPC  128          // samples per CTA
#define TILES 256         // 32768 / 128
#define GRID (TILES*NBK)  // 1280
#define JW   4            // j rows per warp (8 warps x 4 = 32)

typedef unsigned long long u64;

// Weights interleaved [k][j][(i,f,g,o)]: one LDS.128 broadcast = 4 gate weights,
// reused by 4 samples (8 FFMA2 per weight load).
// State [k][col] float4 = samples (c, c+32, c+64, c+96): conflict-free, column-private.
// h0s double-buffered -> 2 barriers per step.
struct SmemLayout {
    float Wp0p[DIN][HD][4];   //  2048 B
    float Wh0p[HD][HD][4];    // 16384 B
    float Wp1p[HD][HD][4];    // 16384 B
    float Wh1p[HD][HD][4];    // 16384 B
    float bp0[HD][4];         //   512 B
    float bp1[HD][4];         //   512 B
    float4 h0s[2][HD][COLS];  // 32768 B (double-buffered)
    float4 h1s[HD][COLS];     // 16384 B
};                            // 101376 B -> 2 CTAs/SM (16 warps)

// MLP overlay offsets (floats) into the weight region (reused after recurrence)
#define OV_W1 0
#define OV_B1 2048
#define OV_W2 2112
#define OV_B2 6208

__device__ __forceinline__ u64 pk2(float v) {
    u64 r; asm("mov.b64 %0, {%1, %1};" : "=l"(r) : "f"(v)); return r;
}
__device__ __forceinline__ u64 f2fma(u64 a, u64 b, u64 c) {
    u64 d; asm("fma.rn.f32x2 %0, %1, %2, %3;" : "=l"(d) : "l"(a), "l"(b), "l"(c));
    return d;
}
__device__ __forceinline__ void unpk(u64 v, float& lo, float& hi) {
    asm("mov.b64 {%0, %1}, %2;" : "=f"(lo), "=f"(hi) : "l"(v));
}
__device__ __forceinline__ float tanhfast(float x) {
    float y; asm("tanh.approx.f32 %0, %1;" : "=f"(y) : "f"(x)); return y;
}
__device__ __forceinline__ float sigf(float v) {
    return fmaf(0.5f, tanhfast(0.5f * v), 0.5f);
}

__global__ void __launch_bounds__(TPB, 2) lstm_fused(
    const float* __restrict__ x,    const float* __restrict__ mask,
    const float* __restrict__ Wih0, const float* __restrict__ Whh0,
    const float* __restrict__ bih0, const float* __restrict__ bhh0,
    const float* __restrict__ Wih1, const float* __restrict__ Whh1,
    const float* __restrict__ bih1, const float* __restrict__ bhh1,
    const float* __restrict__ W1,   const float* __restrict__ b1,
    const float* __restrict__ W2,   const float* __restrict__ b2,
    float* __restrict__ out)
{
    extern __shared__ float smraw[];
    SmemLayout* S = reinterpret_cast<SmemLayout*>(smraw);
    const int tid   = threadIdx.x;
    const int lane  = tid & 31;          // sample column
    const int jbase = (tid >> 5) * JW;   // warp's 4 j rows
    const int ib    = 4 - (blockIdx.x >> 8);        // heavy blocks first
    const int tile  = blockIdx.x & (TILES - 1);

    // ---- stage weights into SMEM (interleaved) ----
    {
        const float* wih0 = Wih0 + ib * 4 * HD * DIN;
        for (int idx = tid; idx < 4 * HD * DIN; idx += TPB) {
            int r = idx / DIN, k = idx % DIN, g = r >> 5, j = r & 31;
            S->Wp0p[k][j][g] = wih0[idx];
        }
        const float* whh0 = Whh0 + ib * 4 * HD * HD;
        const float* wih1 = Wih1 + ib * 4 * HD * HD;
        const float* whh1 = Whh1 + ib * 4 * HD * HD;
        for (int idx = tid; idx < 4 * HD * HD; idx += TPB) {
            int r = idx / HD, k = idx % HD, g = r >> 5, j = r & 31;
            S->Wh0p[k][j][g] = whh0[idx];
            S->Wp1p[k][j][g] = wih1[idx];
            S->Wh1p[k][j][g] = whh1[idx];
        }
        for (int idx = tid; idx < 4 * HD; idx += TPB) {
            int g = idx >> 5, j = idx & 31;
            S->bp0[j][g] = bih0[ib * 4 * HD + idx] + bhh0[ib * 4 * HD + idx];
            S->bp1[j][g] = bih1[ib * 4 * HD + idx] + bhh1[ib * 4 * HD + idx];
        }
        float4* st0 = reinterpret_cast<float4*>(&S->h0s[0][0][0]);
        for (int i = tid; i < HD * COLS; i += TPB) st0[i] = make_float4(0.f, 0.f, 0.f, 0.f);
        float4* st1 = reinterpret_cast<float4*>(&S->h1s[0][0]);
        for (int i = tid; i < HD * COLS; i += TPB) st1[i] = make_float4(0.f, 0.f, 0.f, 0.f);
    }
    __syncthreads();

    float c0r[JW][SPT], c1r[JW][SPT], hnr[JW][SPT];
#pragma unroll
    for (int q = 0; q < JW; q++)
#pragma unroll
        for (int s4 = 0; s4 < SPT; s4++) { c0r[q][s4] = 0.0f; c1r[q][s4] = 0.0f; }

    const int Ti = 5 * (ib + 1);
    // base pointers only (addresses recomputed per step to save registers)
    const float4* xb = reinterpret_cast<const float4*>(x)    + (size_t)(tile * SPC + lane) * TT + (TT - Ti);
    const float4* mb = reinterpret_cast<const float4*>(mask) + (size_t)(tile * SPC + lane) * TT + (TT - Ti);

    for (int st = 0; st < Ti; st++) {
        const int rb = st & 1, wb = 1 - rb;     // h0 double-buffer parity
        float xmf[SPT][DIN];
#pragma unroll
        for (int s4 = 0; s4 < SPT; s4++) {
            float4 xv = __ldg(xb + (size_t)s4 * COLS * TT + st);
            float4 mv = __ldg(mb + (size_t)s4 * COLS * TT + st);
            xmf[s4][0] = xv.x * mv.x; xmf[s4][1] = xv.y * mv.y;
            xmf[s4][2] = xv.z * mv.z; xmf[s4][3] = xv.w * mv.w;
        }

        // ================= layer 0 (reads h0s[rb]) =================
        {
            u64 aI[SPT][JW], aG[SPT][JW];
#pragma unroll
            for (int q = 0; q < JW; q++) {
                ulonglong2 bb = *reinterpret_cast<const ulonglong2*>(S->bp0[jbase + q]);
#pragma unroll
                for (int s4 = 0; s4 < SPT; s4++) { aI[s4][q] = bb.x; aG[s4][q] = bb.y; }
            }
#pragma unroll
            for (int k = 0; k < DIN; k++) {
                u64 hx[SPT];
#pragma unroll
                for (int s4 = 0; s4 < SPT; s4++) hx[s4] = pk2(xmf[s4][k]);
#pragma unroll
                for (int q = 0; q < JW; q++) {
                    ulonglong2 w = *reinterpret_cast<const ulonglong2*>(S->Wp0p[k][jbase + q]);
#pragma unroll
                    for (int s4 = 0; s4 < SPT; s4++) {
                        aI[s4][q] = f2fma(w.x, hx[s4], aI[s4][q]);
                        aG[s4][q] = f2fma(w.y, hx[s4], aG[s4][q]);
                    }
                }
            }
#pragma unroll 8
            for (int k = 0; k < HD; k++) {
                float4 hv = S->h0s[rb][k][lane];
                u64 hh[SPT];
                hh[0] = pk2(hv.x); hh[1] = pk2(hv.y); hh[2] = pk2(hv.z); hh[3] = pk2(hv.w);
#pragma unroll
                for (int q = 0; q < JW; q++) {
                    ulonglong2 w = *reinterpret_cast<const ulonglong2*>(S->Wh0p[k][jbase + q]);
#pragma unroll
                    for (int s4 = 0; s4 < SPT; s4++) {
                        aI[s4][q] = f2fma(w.x, hh[s4], aI[s4][q]);
                        aG[s4][q] = f2fma(w.y, hh[s4], aG[s4][q]);
                    }
                }
            }
#pragma unroll
            for (int q = 0; q < JW; q++) {
#pragma unroll
                for (int s4 = 0; s4 < SPT; s4++) {
                    float ai, af, ag, ao;
                    unpk(aI[s4][q], ai, af); unpk(aG[s4][q], ag, ao);
                    float cc = sigf(af) * c0r[q][s4] + sigf(ai) * tanhfast(ag);
                    c0r[q][s4] = cc;
                    hnr[q][s4] = sigf(ao) * tanhfast(cc);
                }
            }
        }
#pragma unroll
        for (int q = 0; q < JW; q++)
            S->h0s[wb][jbase + q][lane] = make_float4(hnr[q][0], hnr[q][1], hnr[q][2], hnr[q][3]);
        __syncthreads();   // new h0 visible; also orders prev-step h1 writes

        // ================= layer 1 (reads h0s[wb] new + h1s old) =================
        {
            u64 aI[SPT][JW], aG[SPT][JW];
#pragma unroll
            for (int q = 0; q < JW; q++) {
                ulonglong2 bb = *reinterpret_cast<const ulonglong2*>(S->bp1[jbase + q]);
#pragma unroll
                for (int s4 = 0; s4 < SPT; s4++) { aI[s4][q] = bb.x; aG[s4][q] = bb.y; }
            }
#pragma unroll 8
            for (int k = 0; k < HD; k++) {
                float4 hv = S->h0s[wb][k][lane];
                u64 hh[SPT];
                hh[0] = pk2(hv.x); hh[1] = pk2(hv.y); hh[2] = pk2(hv.z); hh[3] = pk2(hv.w);
#pragma unroll
                for (int q = 0; q < JW; q++) {
                    ulonglong2 w = *reinterpret_cast<const ulonglong2*>(S->Wp1p[k][jbase + q]);
#pragma unroll
                    for (int s4 = 0; s4 < SPT; s4++) {
                        aI[s4][q] = f2fma(w.x, hh[s4], aI[s4][q]);
                        aG[s4][q] = f2fma(w.y, hh[s4], aG[s4][q]);
                    }
                }
            }
#pragma unroll 8
            for (int k = 0; k < HD; k++) {
                float4 hv = S->h1s[k][lane];
                u64 hh[SPT];
                hh[0] = pk2(hv.x); hh[1] = pk2(hv.y); hh[2] = pk2(hv.z); hh[3] = pk2(hv.w);
#pragma unroll
                for (int q = 0; q < JW; q++) {
                    ulonglong2 w = *reinterpret_cast<const ulonglong2*>(S->Wh1p[k][jbase + q]);
#pragma unroll
                    for (int s4 = 0; s4 < SPT; s4++) {
                        aI[s4][q] = f2fma(w.x, hh[s4], aI[s4][q]);
                        aG[s4][q] = f2fma(w.y, hh[s4], aG[s4][q]);
                    }
                }
            }
#pragma unroll
            for (int q = 0; q < JW; q++) {
#pragma unroll
                for (int s4 = 0; s4 < SPT; s4++) {
                    float ai, af, ag, ao;
                    unpk(aI[s4][q], ai, af); unpk(aG[s4][q], ag, ao);
                    float cc = sigf(af) * c1r[q][s4] + sigf(ai) * tanhfast(ag);
                    c1r[q][s4] = cc;
                    hnr[q][s4] = sigf(ao) * tanhfast(cc);
                }
            }
        }
        __syncthreads();   // all layer-1 reads of old h1s complete
#pragma unroll
        for (int q = 0; q < JW; q++)
            S->h1s[jbase + q][lane] = make_float4(hnr[q][0], hnr[q][1], hnr[q][2], hnr[q][3]);
        // h1 writes ordered for next step's L1 by the first barrier of next step
    }

    // ---- MLP head: 2 threads per sample ----
    __syncthreads();   // h1s final visible; weight region about to be reused
    float* ov = smraw;
    for (int idx = tid; idx < HIDD * HD; idx += TPB)   ov[OV_W1 + idx] = W1[idx];
    for (int idx = tid; idx < HIDD * HIDD; idx += TPB) {
        int n = idx / HIDD, m = idx % HIDD;
        ov[OV_W2 + m * HIDD + n] = W2[idx];            // transposed [m][n]
    }
    if (tid < HIDD) { ov[OV_B1 + tid] = b1[tid]; ov[OV_B2 + tid] = b2[tid]; }
    __syncthreads();

    const int sidx = tid & 127;      // sample within CTA
    const int half = tid >> 7;       // which 32 outputs
    const int scol = sidx & 31;
    const int sq   = sidx >> 5;      // float4 component

    float hr[HD];
#pragma unroll
    for (int k = 0; k < HD; k++) {
        float4 v = S->h1s[k][scol];
        hr[k] = (sq == 0) ? v.x : (sq == 1) ? v.y : (sq == 2) ? v.z : v.w;
    }

    float acc2[HIDD / 2];
#pragma unroll
    for (int n = 0; n < HIDD / 2; n++) acc2[n] = ov[OV_B2 + half * (HIDD / 2) + n];

    for (int m = 0; m < HIDD; m++) {
        float tm = ov[OV_B1 + m];
        const float4* w1r = reinterpret_cast<const float4*>(&ov[OV_W1 + m * HD]);
#pragma unroll
        for (int q = 0; q < HD / 4; q++) {
            float4 w = w1r[q];
            tm += hr[4 * q + 0] * w.x + hr[4 * q + 1] * w.y
                + hr[4 * q + 2] * w.z + hr[4 * q + 3] * w.w;
        }
        tm = 0.5f * tm * (1.0f + erff(tm * 0.70710678118654752f));   // exact gelu
        const float4* w2r = reinterpret_cast<const float4*>(
            &ov[OV_W2 + m * HIDD + half * (HIDD / 2)]);
#pragma unroll
        for (int q = 0; q < HIDD / 8; q++) {
            float4 w = w2r[q];
            acc2[4 * q + 0] += tm * w.x; acc2[4 * q + 1] += tm * w.y;
            acc2[4 * q + 2] += tm * w.z; acc2[4 * q + 3] += tm * w.w;
        }
    }

    const int bS = tile * SPC + sidx;
    float4* op = reinterpret_cast<float4*>(
        out + ((size_t)bS * NBK + ib) * HIDD + half * (HIDD / 2));
#pragma unroll
    for (int q = 0; q < HIDD / 8; q++)
        op[q] = make_float4(acc2[4 * q], acc2[4 * q + 1],
                            acc2[4 * q + 2], acc2[4 * q + 3]);
}

extern "C" void kernel_launch(void* const* d_in, const int* in_sizes, int n_in,
                              void* d_out, int out_size)
{
    const float* x    = (const float*)d_in[0];
    const float* mask = (const float*)d_in[1];
    const float* Wih0 = (const float*)d_in[2];
    const float* Whh0 = (const float*)d_in[3];
    const float* bih0 = (const float*)d_in[4];
    const float* bhh0 = (const float*)d_in[5];
    const float* Wih1 = (const float*)d_in[6];
    const float* Whh1 = (const float*)d_in[7];
    const float* bih1 = (const float*)d_in[8];
    const float* bhh1 = (const float*)d_in[9];
    const float* W1   = (const float*)d_in[10];
    const float* b1   = (const float*)d_in[11];
    const float* W2   = (const float*)d_in[12];
    const float* b2   = (const float*)d_in[13];
    float* out = (float*)d_out;

    const size_t smem = sizeof(SmemLayout);   // 101376 B -> 2 CTAs/SM
    cudaFuncSetAttribute(lstm_fused, cudaFuncAttributeMaxDynamicSharedMemorySize,
                         (int)smem);
    lstm_fused<<<GRID, TPB, smem>>>(x, mask, Wih0, Whh0, bih0, bhh0,
                                    Wih1, Whh1, bih1, bhh1, W1, b1, W2, b2, out);
}

// round 9
// speedup vs baseline: 1.0855x; 1.0855x over previous
#include <cuda_runtime.h>
#include <math.h>

#define NBK  5
#define HD   32
#define DIN  4
#define TT   25
#define HIDD 64
#define TPB  128          // 4 warps
#define COLS 32           // lanes = sample columns
#define SPT  4            // samples per thread (float4-packed)
#define SPC  128          // samples per CTA
#define TILES 256         // 32768 / 128
#define GRID (TILES*NBK)  // 1280
#define JW   8            // j rows per warp
#define JB   4            // j per pass (2 passes)

typedef unsigned long long u64;

// Weights interleaved [k][j][(i,f,g,o)]: one LDS.128 broadcast = 4 gate weights,
// reused by 4 samples (8 FFMA2 per weight load).
// BOTH h-states double-buffered -> exactly ONE __syncthreads per timestep.
// Wp0 (layer-0 input weights, 2KB) lives in a pre-interleaved __device__ global
// (L1-resident broadcast LDG) to keep smem <= 113KB for 2 CTAs/SM.
struct SmemLayout {
    float Wh0p[HD][HD][4];    // 16384 B
    float Wp1p[HD][HD][4];    // 16384 B
    float Wh1p[HD][HD][4];    // 16384 B
    float bp0[HD][4];         //   512 B
    float bp1[HD][4];         //   512 B
    float4 h0s[2][HD][COLS];  // 32768 B (double-buffered)
    float4 h1s[2][HD][COLS];  // 32768 B (double-buffered)
};                            // 115712 B -> 2 CTAs/SM (8 warps)

// MLP overlay offsets (floats) into the weight region (reused after recurrence)
#define OV_W1 0
#define OV_B1 2048
#define OV_W2 2112
#define OV_B2 6208

// Pre-interleaved layer-0 input weights: g_wp0[ib][k][j][gate]
__device__ __align__(16) float g_wp0[NBK][DIN][HD][4];

__global__ void prep_kernel(const float* __restrict__ Wih0) {
    const int i = blockIdx.x;
    for (int idx = threadIdx.x; idx < 4 * HD * DIN; idx += blockDim.x) {
        int r = idx / DIN, k = idx % DIN, g = r >> 5, j = r & 31;
        g_wp0[i][k][j][g] = Wih0[i * 4 * HD * DIN + idx];
    }
}

__device__ __forceinline__ u64 pk2(float v) {
    u64 r; asm("mov.b64 %0, {%1, %1};" : "=l"(r) : "f"(v)); return r;
}
__device__ __forceinline__ u64 f2fma(u64 a, u64 b, u64 c) {
    u64 d; asm("fma.rn.f32x2 %0, %1, %2, %3;" : "=l"(d) : "l"(a), "l"(b), "l"(c));
    return d;
}
__device__ __forceinline__ void unpk(u64 v, float& lo, float& hi) {
    asm("mov.b64 {%0, %1}, %2;" : "=f"(lo), "=f"(hi) : "l"(v));
}
__device__ __forceinline__ float tanhfast(float x) {
    float y; asm("tanh.approx.f32 %0, %1;" : "=f"(y) : "f"(x)); return y;
}
__device__ __forceinline__ float sigf(float v) {
    return fmaf(0.5f, tanhfast(0.5f * v), 0.5f);
}

__global__ void __launch_bounds__(TPB, 2) lstm_fused(
    const float* __restrict__ x,    const float* __restrict__ mask,
    const float* __restrict__ Wih0, const float* __restrict__ Whh0,
    const float* __restrict__ bih0, const float* __restrict__ bhh0,
    const float* __restrict__ Wih1, const float* __restrict__ Whh1,
    const float* __restrict__ bih1, const float* __restrict__ bhh1,
    const float* __restrict__ W1,   const float* __restrict__ b1,
    const float* __restrict__ W2,   const float* __restrict__ b2,
    float* __restrict__ out)
{
    extern __shared__ float smraw[];
    SmemLayout* S = reinterpret_cast<SmemLayout*>(smraw);
    const int tid   = threadIdx.x;
    const int lane  = tid & 31;          // sample column
    const int jbase = (tid >> 5) * JW;   // warp's j rows
    const int ib    = 4 - (blockIdx.x >> 8);        // heavy blocks first
    const int tile  = blockIdx.x & (TILES - 1);

    // ---- stage weights into SMEM (interleaved) ----
    {
        const float* whh0 = Whh0 + ib * 4 * HD * HD;
        const float* wih1 = Wih1 + ib * 4 * HD * HD;
        const float* whh1 = Whh1 + ib * 4 * HD * HD;
        for (int idx = tid; idx < 4 * HD * HD; idx += TPB) {
            int r = idx / HD, k = idx % HD, g = r >> 5, j = r & 31;
            S->Wh0p[k][j][g] = whh0[idx];
            S->Wp1p[k][j][g] = wih1[idx];
            S->Wh1p[k][j][g] = whh1[idx];
        }
        for (int idx = tid; idx < 4 * HD; idx += TPB) {
            int g = idx >> 5, j = idx & 31;
            S->bp0[j][g] = bih0[ib * 4 * HD + idx] + bhh0[ib * 4 * HD + idx];
            S->bp1[j][g] = bih1[ib * 4 * HD + idx] + bhh1[ib * 4 * HD + idx];
        }
        // zero read-buffers (buffer 0); write-buffers are write-before-read
        float4* st0 = reinterpret_cast<float4*>(&S->h0s[0][0][0]);
        for (int i = tid; i < HD * COLS; i += TPB) st0[i] = make_float4(0.f, 0.f, 0.f, 0.f);
        float4* st1 = reinterpret_cast<float4*>(&S->h1s[0][0][0]);
        for (int i = tid; i < HD * COLS; i += TPB) st1[i] = make_float4(0.f, 0.f, 0.f, 0.f);
    }
    __syncthreads();

    float c0r[JW][SPT], c1r[JW][SPT], hnr[JW][SPT];
#pragma unroll
    for (int q = 0; q < JW; q++)
#pragma unroll
        for (int s4 = 0; s4 < SPT; s4++) { c0r[q][s4] = 0.0f; c1r[q][s4] = 0.0f; }

    const int Ti = 5 * (ib + 1);
    const float4* xp[SPT]; const float4* mp[SPT];
    float4 xv[SPT], mv[SPT];
#pragma unroll
    for (int s4 = 0; s4 < SPT; s4++) {
        const int b = tile * SPC + lane + s4 * COLS;
        xp[s4] = reinterpret_cast<const float4*>(x)    + (size_t)b * TT + (TT - Ti);
        mp[s4] = reinterpret_cast<const float4*>(mask) + (size_t)b * TT + (TT - Ti);
        xv[s4] = __ldg(xp[s4]); mv[s4] = __ldg(mp[s4]);
    }

    for (int st = 0; st < Ti; st++) {
        const int rb = st & 1, wb = 1 - rb;     // double-buffer parity (both layers)
        float xmf[SPT][DIN];
#pragma unroll
        for (int s4 = 0; s4 < SPT; s4++) {
            xmf[s4][0] = xv[s4].x * mv[s4].x; xmf[s4][1] = xv[s4].y * mv[s4].y;
            xmf[s4][2] = xv[s4].z * mv[s4].z; xmf[s4][3] = xv[s4].w * mv[s4].w;
        }
        if (st + 1 < Ti) {
#pragma unroll
            for (int s4 = 0; s4 < SPT; s4++) {
                xv[s4] = __ldg(xp[s4] + st + 1); mv[s4] = __ldg(mp[s4] + st + 1);
            }
        }

        // ================= layer 0 (reads h0s[rb], writes h0s[wb]) =================
#pragma unroll
        for (int p = 0; p < JW / JB; p++) {
            u64 aI[SPT][JB], aG[SPT][JB];
#pragma unroll
            for (int q = 0; q < JB; q++) {
                ulonglong2 bb = *reinterpret_cast<const ulonglong2*>(S->bp0[jbase + p * JB + q]);
#pragma unroll
                for (int s4 = 0; s4 < SPT; s4++) { aI[s4][q] = bb.x; aG[s4][q] = bb.y; }
            }
#pragma unroll
            for (int k = 0; k < DIN; k++) {
                u64 hx[SPT];
#pragma unroll
                for (int s4 = 0; s4 < SPT; s4++) hx[s4] = pk2(xmf[s4][k]);
#pragma unroll
                for (int q = 0; q < JB; q++) {
                    ulonglong2 w = __ldg(reinterpret_cast<const ulonglong2*>(
                        &g_wp0[ib][k][jbase + p * JB + q][0]));
#pragma unroll
                    for (int s4 = 0; s4 < SPT; s4++) {
                        aI[s4][q] = f2fma(w.x, hx[s4], aI[s4][q]);
                        aG[s4][q] = f2fma(w.y, hx[s4], aG[s4][q]);
                    }
                }
            }
#pragma unroll 8
            for (int k = 0; k < HD; k++) {
                float4 hv = S->h0s[rb][k][lane];
                u64 hh[SPT];
                hh[0] = pk2(hv.x); hh[1] = pk2(hv.y); hh[2] = pk2(hv.z); hh[3] = pk2(hv.w);
#pragma unroll
                for (int q = 0; q < JB; q++) {
                    ulonglong2 w = *reinterpret_cast<const ulonglong2*>(S->Wh0p[k][jbase + p * JB + q]);
#pragma unroll
                    for (int s4 = 0; s4 < SPT; s4++) {
                        aI[s4][q] = f2fma(w.x, hh[s4], aI[s4][q]);
                        aG[s4][q] = f2fma(w.y, hh[s4], aG[s4][q]);
                    }
                }
            }
#pragma unroll
            for (int q = 0; q < JB; q++) {
                const int idx = p * JB + q;
#pragma unroll
                for (int s4 = 0; s4 < SPT; s4++) {
                    float ai, af, ag, ao;
                    unpk(aI[s4][q], ai, af); unpk(aG[s4][q], ag, ao);
                    float cc = sigf(af) * c0r[idx][s4] + sigf(ai) * tanhfast(ag);
                    c0r[idx][s4] = cc;
                    hnr[idx][s4] = sigf(ao) * tanhfast(cc);
                }
            }
        }
#pragma unroll
        for (int q = 0; q < JW; q++)
            S->h0s[wb][jbase + q][lane] = make_float4(hnr[q][0], hnr[q][1], hnr[q][2], hnr[q][3]);
        __syncthreads();   // THE one barrier: h0[wb] (and prev-step h1[.]) visible

        // ========== layer 1 (reads h0s[wb] + h1s[rb], writes h1s[wb]) ==========
#pragma unroll
        for (int p = 0; p < JW / JB; p++) {
            u64 aI[SPT][JB], aG[SPT][JB];
#pragma unroll
            for (int q = 0; q < JB; q++) {
                ulonglong2 bb = *reinterpret_cast<const ulonglong2*>(S->bp1[jbase + p * JB + q]);
#pragma unroll
                for (int s4 = 0; s4 < SPT; s4++) { aI[s4][q] = bb.x; aG[s4][q] = bb.y; }
            }
#pragma unroll 8
            for (int k = 0; k < HD; k++) {
                float4 hv = S->h0s[wb][k][lane];
                u64 hh[SPT];
                hh[0] = pk2(hv.x); hh[1] = pk2(hv.y); hh[2] = pk2(hv.z); hh[3] = pk2(hv.w);
#pragma unroll
                for (int q = 0; q < JB; q++) {
                    ulonglong2 w = *reinterpret_cast<const ulonglong2*>(S->Wp1p[k][jbase + p * JB + q]);
#pragma unroll
                    for (int s4 = 0; s4 < SPT; s4++) {
                        aI[s4][q] = f2fma(w.x, hh[s4], aI[s4][q]);
                        aG[s4][q] = f2fma(w.y, hh[s4], aG[s4][q]);
                    }
                }
            }
#pragma unroll 8
            for (int k = 0; k < HD; k++) {
                float4 hv = S->h1s[rb][k][lane];
                u64 hh[SPT];
                hh[0] = pk2(hv.x); hh[1] = pk2(hv.y); hh[2] = pk2(hv.z); hh[3] = pk2(hv.w);
#pragma unroll
                for (int q = 0; q < JB; q++) {
                    ulonglong2 w = *reinterpret_cast<const ulonglong2*>(S->Wh1p[k][jbase + p * JB + q]);
#pragma unroll
                    for (int s4 = 0; s4 < SPT; s4++) {
                        aI[s4][q] = f2fma(w.x, hh[s4], aI[s4][q]);
                        aG[s4][q] = f2fma(w.y, hh[s4], aG[s4][q]);
                    }
                }
            }
#pragma unroll
            for (int q = 0; q < JB; q++) {
                const int idx = p * JB + q;
#pragma unroll
                for (int s4 = 0; s4 < SPT; s4++) {
                    float ai, af, ag, ao;
                    unpk(aI[s4][q], ai, af); unpk(aG[s4][q], ag, ao);
                    float cc = sigf(af) * c1r[idx][s4] + sigf(ai) * tanhfast(ag);
                    c1r[idx][s4] = cc;
                    hnr[idx][s4] = sigf(ao) * tanhfast(cc);
                }
            }
        }
#pragma unroll
        for (int q = 0; q < JW; q++)
            S->h1s[wb][jbase + q][lane] = make_float4(hnr[q][0], hnr[q][1], hnr[q][2], hnr[q][3]);
        // h1[wb] visibility for next step's layer-1 is provided by next step's barrier
    }

    // ---- MLP head: 1 thread per sample ----
    __syncthreads();   // final h1 visible; weight region about to be reused
    const int fb = 1 - ((Ti - 1) & 1);   // buffer holding final h1

    float* ov = smraw;
    for (int idx = tid; idx < HIDD * HD; idx += TPB)   ov[OV_W1 + idx] = W1[idx];
    for (int idx = tid; idx < HIDD * HIDD; idx += TPB) {
        int n = idx / HIDD, m = idx % HIDD;
        ov[OV_W2 + m * HIDD + n] = W2[idx];            // transposed [m][n]
    }
    if (tid < HIDD) { ov[OV_B1 + tid] = b1[tid]; ov[OV_B2 + tid] = b2[tid]; }
    __syncthreads();

    const int scol = tid & 31;
    const int sq   = tid >> 5;       // which float4 component

    float hr[HD];
#pragma unroll
    for (int k = 0; k < HD; k++) {
        float4 v = S->h1s[fb][k][scol];
        hr[k] = (sq == 0) ? v.x : (sq == 1) ? v.y : (sq == 2) ? v.z : v.w;
    }

    float acc2[HIDD];
#pragma unroll
    for (int n = 0; n < HIDD; n++) acc2[n] = ov[OV_B2 + n];

    for (int m = 0; m < HIDD; m++) {
        float tm = ov[OV_B1 + m];
        const float4* w1r = reinterpret_cast<const float4*>(&ov[OV_W1 + m * HD]);
#pragma unroll
        for (int q = 0; q < HD / 4; q++) {
            float4 w = w1r[q];
            tm += hr[4 * q + 0] * w.x + hr[4 * q + 1] * w.y
                + hr[4 * q + 2] * w.z + hr[4 * q + 3] * w.w;
        }
        tm = 0.5f * tm * (1.0f + erff(tm * 0.70710678118654752f));   // exact gelu
        const float4* w2r = reinterpret_cast<const float4*>(&ov[OV_W2 + m * HIDD]);
#pragma unroll
        for (int q = 0; q < HIDD / 4; q++) {
            float4 w = w2r[q];
            acc2[4 * q + 0] += tm * w.x; acc2[4 * q + 1] += tm * w.y;
            acc2[4 * q + 2] += tm * w.z; acc2[4 * q + 3] += tm * w.w;
        }
    }

    const int bS = tile * SPC + sq * COLS + scol;
    float4* op = reinterpret_cast<float4*>(out + ((size_t)bS * NBK + ib) * HIDD);
#pragma unroll
    for (int q = 0; q < HIDD / 4; q++)
        op[q] = make_float4(acc2[4 * q], acc2[4 * q + 1],
                            acc2[4 * q + 2], acc2[4 * q + 3]);
}

extern "C" void kernel_launch(void* const* d_in, const int* in_sizes, int n_in,
                              void* d_out, int out_size)
{
    const float* x    = (const float*)d_in[0];
    const float* mask = (const float*)d_in[1];
    const float* Wih0 = (const float*)d_in[2];
    const float* Whh0 = (const float*)d_in[3];
    const float* bih0 = (const float*)d_in[4];
    const float* bhh0 = (const float*)d_in[5];
    const float* Wih1 = (const float*)d_in[6];
    const float* Whh1 = (const float*)d_in[7];
    const float* bih1 = (const float*)d_in[8];
    const float* bhh1 = (const float*)d_in[9];
    const float* W1   = (const float*)d_in[10];
    const float* b1   = (const float*)d_in[11];
    const float* W2   = (const float*)d_in[12];
    const float* b2   = (const float*)d_in[13];
    float* out = (float*)d_out;

    prep_kernel<<<NBK, 128>>>(Wih0);   // interleave Wp0 into g_wp0 (graph-safe)

    const size_t smem = sizeof(SmemLayout);   // 115712 B -> 2 CTAs/SM
    cudaFuncSetAttribute(lstm_fused, cudaFuncAttributeMaxDynamicSharedMemorySize,
                         (int)smem);
    lstm_fused<<<GRID, TPB, smem>>>(x, mask, Wih0, Whh0, bih0, bhh0,
                                    Wih1, Whh1, bih1, bhh1, W1, b1, W2, b2, out);
}